// round 12
// baseline (speedup 1.0000x reference)
#include <cuda_runtime.h>
#include <cuda_fp16.h>
#include <cuda_bf16.h>
#include <cstdint>

#define N_NODES 100000
#define F_IN 256
#define F_OUT 256
#define MAX_E 3200000

#define SCAN_CHUNK 1024
#define N_CHUNKS ((N_NODES + SCAN_CHUNK - 1) / SCAN_CHUNK)   // 98

// ---- device scratch ----
__device__ __half g_support_h[(size_t)N_NODES * F_OUT];  // 51.2 MB (fp16)
__device__ int2   g_edata[MAX_E];                        // packed (col, val)
__device__ int    g_counts[N_NODES];
__device__ int    g_offsets[N_NODES + 1];
__device__ int    g_cursor[N_NODES];
__device__ int    g_blocksums[N_CHUNKS];

// ---------------------------------------------------------------------------
// Stage 1: TF32 tensor-core GEMM  C[M,256] = A[M,256] @ B[256,256]
// ---------------------------------------------------------------------------
#define GBM 128
#define GBN 128
#define GBK 32
#define AS_STRIDE 36
#define BS_STRIDE 136

__device__ __forceinline__ uint32_t f32_to_tf32(float f)
{
    uint32_t u;
    asm volatile("cvt.rna.tf32.f32 %0, %1;" : "=r"(u) : "f"(f));
    return u;
}

__device__ __forceinline__ void mma_tf32(
    float& d0, float& d1, float& d2, float& d3,
    uint32_t a0, uint32_t a1, uint32_t a2, uint32_t a3,
    uint32_t b0, uint32_t b1)
{
    asm volatile(
        "mma.sync.aligned.m16n8k8.row.col.f32.tf32.tf32.f32 "
        "{%0,%1,%2,%3}, {%4,%5,%6,%7}, {%8,%9}, {%0,%1,%2,%3};\n"
        : "+f"(d0), "+f"(d1), "+f"(d2), "+f"(d3)
        : "r"(a0), "r"(a1), "r"(a2), "r"(a3), "r"(b0), "r"(b1));
}

__global__ void __launch_bounds__(256) gemm_tc_kernel(
    const float* __restrict__ A,
    const float* __restrict__ B,
    __half* __restrict__ C,
    int M)
{
    __shared__ uint32_t As[GBM][AS_STRIDE];
    __shared__ uint32_t Bs[GBK][BS_STRIDE];

    const int tid = threadIdx.x;
    const int lane = tid & 31;
    const int warp = tid >> 5;
    const int warpRow = warp >> 2;
    const int warpCol = warp & 3;
    const int blockRow = blockIdx.y * GBM;
    const int blockCol = blockIdx.x * GBN;

    const int lq = lane >> 2;
    const int lr = lane & 3;

    float d[4][4][4];
#pragma unroll
    for (int mt = 0; mt < 4; mt++)
#pragma unroll
        for (int nt = 0; nt < 4; nt++)
#pragma unroll
            for (int r = 0; r < 4; r++) d[mt][nt][r] = 0.0f;

    for (int k0 = 0; k0 < F_IN; k0 += GBK) {
#pragma unroll
        for (int i = 0; i < 4; i++) {
            int idx = tid + i * 256;
            int row = idx >> 3;
            int kc = (idx & 7) * 4;
            int gr = blockRow + row;
            float4 a4 = make_float4(0.f, 0.f, 0.f, 0.f);
            if (gr < M)
                a4 = *reinterpret_cast<const float4*>(A + (size_t)gr * F_IN + k0 + kc);
            uint4 t;
            t.x = f32_to_tf32(a4.x);
            t.y = f32_to_tf32(a4.y);
            t.z = f32_to_tf32(a4.z);
            t.w = f32_to_tf32(a4.w);
            *reinterpret_cast<uint4*>(&As[row][kc]) = t;
        }
#pragma unroll
        for (int i = 0; i < 4; i++) {
            int idx = tid + i * 256;
            int row = idx >> 5;
            int cc = (idx & 31) * 4;
            float4 b4 = *reinterpret_cast<const float4*>(
                B + (size_t)(k0 + row) * F_OUT + blockCol + cc);
            uint4 t;
            t.x = f32_to_tf32(b4.x);
            t.y = f32_to_tf32(b4.y);
            t.z = f32_to_tf32(b4.z);
            t.w = f32_to_tf32(b4.w);
            *reinterpret_cast<uint4*>(&Bs[row][cc]) = t;
        }
        __syncthreads();

#pragma unroll
        for (int kk = 0; kk < GBK; kk += 8) {
            uint32_t af[4][4];
#pragma unroll
            for (int mt = 0; mt < 4; mt++) {
                int r0 = warpRow * 64 + mt * 16 + lq;
                af[mt][0] = As[r0][kk + lr];
                af[mt][1] = As[r0 + 8][kk + lr];
                af[mt][2] = As[r0][kk + lr + 4];
                af[mt][3] = As[r0 + 8][kk + lr + 4];
            }
            uint32_t bf[4][2];
#pragma unroll
            for (int nt = 0; nt < 4; nt++) {
                int n0 = warpCol * 32 + nt * 8 + lq;
                bf[nt][0] = Bs[kk + lr][n0];
                bf[nt][1] = Bs[kk + lr + 4][n0];
            }
#pragma unroll
            for (int mt = 0; mt < 4; mt++)
#pragma unroll
                for (int nt = 0; nt < 4; nt++)
                    mma_tf32(d[mt][nt][0], d[mt][nt][1], d[mt][nt][2], d[mt][nt][3],
                             af[mt][0], af[mt][1], af[mt][2], af[mt][3],
                             bf[nt][0], bf[nt][1]);
        }
        __syncthreads();
    }

#pragma unroll
    for (int mt = 0; mt < 4; mt++) {
        int r0 = blockRow + warpRow * 64 + mt * 16 + lq;
        int r1 = r0 + 8;
#pragma unroll
        for (int nt = 0; nt < 4; nt++) {
            int c = blockCol + warpCol * 32 + nt * 8 + 2 * lr;
            if (r0 < M)
                *reinterpret_cast<__half2*>(C + (size_t)r0 * F_OUT + c) =
                    __floats2half2_rn(d[mt][nt][0], d[mt][nt][1]);
            if (r1 < M)
                *reinterpret_cast<__half2*>(C + (size_t)r1 * F_OUT + c) =
                    __floats2half2_rn(d[mt][nt][2], d[mt][nt][3]);
        }
    }
}

// ---------------------------------------------------------------------------
// Counting sort of edges by row
// ---------------------------------------------------------------------------
__global__ void zero_counts_kernel(int* __restrict__ counts, int n)
{
    int i = blockIdx.x * blockDim.x + threadIdx.x;
    if (i < n) counts[i] = 0;
}

__global__ void hist_kernel(const int* __restrict__ rows, int* __restrict__ counts, int E)
{
    const int4* r4 = reinterpret_cast<const int4*>(rows);
    int n4 = E >> 2;
    int i = blockIdx.x * blockDim.x + threadIdx.x;
    int stride = gridDim.x * blockDim.x;
    for (; i < n4; i += stride) {
        int4 r = __ldcs(&r4[i]);
        atomicAdd(&counts[r.x], 1);
        atomicAdd(&counts[r.y], 1);
        atomicAdd(&counts[r.z], 1);
        atomicAdd(&counts[r.w], 1);
    }
    int t = n4 * 4 + (blockIdx.x * blockDim.x + threadIdx.x);
    if (t < E) atomicAdd(&counts[rows[t]], 1);
}

__global__ void __launch_bounds__(1024) scan_pass1(
    const int* __restrict__ counts,
    int* __restrict__ offsets,
    int* __restrict__ blocksums, int n)
{
    __shared__ int sdata[SCAN_CHUNK];
    int tid = threadIdx.x;
    int i = blockIdx.x * SCAN_CHUNK + tid;
    int x = (i < n) ? counts[i] : 0;
    sdata[tid] = x;
    __syncthreads();
#pragma unroll
    for (int off = 1; off < SCAN_CHUNK; off <<= 1) {
        int t = (tid >= off) ? sdata[tid - off] : 0;
        __syncthreads();
        sdata[tid] += t;
        __syncthreads();
    }
    if (i < n) offsets[i] = sdata[tid] - x;
    if (tid == SCAN_CHUNK - 1) blocksums[blockIdx.x] = sdata[tid];
}

__global__ void scan_pass2(int* __restrict__ blocksums, int* __restrict__ total_out, int nchunks)
{
    __shared__ int sdata[128];
    int tid = threadIdx.x;
    int x = (tid < nchunks) ? blocksums[tid] : 0;
    sdata[tid] = x;
    __syncthreads();
#pragma unroll
    for (int off = 1; off < 128; off <<= 1) {
        int t = (tid >= off) ? sdata[tid - off] : 0;
        __syncthreads();
        sdata[tid] += t;
        __syncthreads();
    }
    if (tid < nchunks) blocksums[tid] = sdata[tid] - x;
    if (tid == 127) *total_out = sdata[127];
}

__global__ void __launch_bounds__(1024) scan_pass3(
    int* __restrict__ offsets,
    int* __restrict__ cursor,
    const int* __restrict__ blocksums, int n)
{
    int i = blockIdx.x * SCAN_CHUNK + threadIdx.x;
    if (i < n) {
        int v = offsets[i] + blocksums[blockIdx.x];
        offsets[i] = v;
        cursor[i] = v;
    }
}

__global__ void scatter_kernel(const int* __restrict__ rows,
                               const int* __restrict__ cols,
                               const float* __restrict__ vals,
                               int* __restrict__ cursor,
                               int2* __restrict__ edata, int E)
{
    const int4*   r4 = reinterpret_cast<const int4*>(rows);
    const int4*   c4 = reinterpret_cast<const int4*>(cols);
    const float4* v4 = reinterpret_cast<const float4*>(vals);
    int n4 = E >> 2;
    int i = blockIdx.x * blockDim.x + threadIdx.x;
    int stride = gridDim.x * blockDim.x;
    for (; i < n4; i += stride) {
        int4   r = __ldcs(&r4[i]);
        int4   c = __ldcs(&c4[i]);
        float4 v = __ldcs(&v4[i]);
        int p0 = atomicAdd(&cursor[r.x], 1);
        int p1 = atomicAdd(&cursor[r.y], 1);
        int p2 = atomicAdd(&cursor[r.z], 1);
        int p3 = atomicAdd(&cursor[r.w], 1);
        edata[p0] = make_int2(c.x, __float_as_int(v.x));
        edata[p1] = make_int2(c.y, __float_as_int(v.y));
        edata[p2] = make_int2(c.z, __float_as_int(v.z));
        edata[p3] = make_int2(c.w, __float_as_int(v.w));
    }
    int t = n4 * 4 + (blockIdx.x * blockDim.x + threadIdx.x);
    if (t < E) {
        int r = rows[t];
        int pos = atomicAdd(&cursor[r], 1);
        edata[pos] = make_int2(cols[t], __float_as_int(vals[t]));
    }
}

// ---------------------------------------------------------------------------
// Stage 3: warp-per-node segmented reduction, 8-edge unroll (MLP=8).
// ---------------------------------------------------------------------------
__device__ __forceinline__ void acc_edge(float (&acc)[8], float v, const uint4& p)
{
    const __half2* h = reinterpret_cast<const __half2*>(&p);
#pragma unroll
    for (int j = 0; j < 4; j++) {
        float2 f = __half22float2(h[j]);
        acc[2 * j]     = fmaf(v, f.x, acc[2 * j]);
        acc[2 * j + 1] = fmaf(v, f.y, acc[2 * j + 1]);
    }
}

__global__ void __launch_bounds__(256) gather_reduce_kernel(
    const int* __restrict__ offsets,
    const int2* __restrict__ edata,
    const __half* __restrict__ sup,
    const float* __restrict__ bias,
    float* __restrict__ out,
    int M)
{
    int warp = (int)((blockIdx.x * blockDim.x + threadIdx.x) >> 5);
    int lane = threadIdx.x & 31;
    if (warp >= M) return;

    int start = offsets[warp];
    int end   = offsets[warp + 1];

    float acc[8];
#pragma unroll
    for (int j = 0; j < 8; j++) acc[j] = 0.0f;

    int e = start;
    int e8end = start + ((end - start) & ~7);
    for (; e < e8end; e += 8) {
        int2 ed[8];
#pragma unroll
        for (int u = 0; u < 8; u++) ed[u] = __ldcs(&edata[e + u]);
        uint4 p[8];
#pragma unroll
        for (int u = 0; u < 8; u++)
            p[u] = reinterpret_cast<const uint4*>(sup + (size_t)ed[u].x * F_OUT)[lane];
#pragma unroll
        for (int u = 0; u < 8; u++)
            acc_edge(acc, __int_as_float(ed[u].y), p[u]);
    }
    int e4end = start + ((end - start) & ~3);
    if (e < e4end) {
        int2 ed[4];
#pragma unroll
        for (int u = 0; u < 4; u++) ed[u] = __ldcs(&edata[e + u]);
        uint4 p[4];
#pragma unroll
        for (int u = 0; u < 4; u++)
            p[u] = reinterpret_cast<const uint4*>(sup + (size_t)ed[u].x * F_OUT)[lane];
#pragma unroll
        for (int u = 0; u < 4; u++)
            acc_edge(acc, __int_as_float(ed[u].y), p[u]);
        e = e4end;
    }
    for (; e < end; e++) {
        int2 ed = __ldcs(&edata[e]);
        uint4 p = reinterpret_cast<const uint4*>(sup + (size_t)ed.x * F_OUT)[lane];
        acc_edge(acc, __int_as_float(ed.y), p);
    }

    const float4* b4 = reinterpret_cast<const float4*>(bias) + lane * 2;
    float4 bb0 = b4[0];
    float4 bb1 = b4[1];
    float4 o0 = make_float4(acc[0] + bb0.x, acc[1] + bb0.y, acc[2] + bb0.z, acc[3] + bb0.w);
    float4 o1 = make_float4(acc[4] + bb1.x, acc[5] + bb1.y, acc[6] + bb1.z, acc[7] + bb1.w);

    float4* orow = reinterpret_cast<float4*>(out + (size_t)warp * F_OUT) + lane * 2;
    __stcs(&orow[0], o0);
    __stcs(&orow[1], o1);
}

// ---------------------------------------------------------------------------
extern "C" void kernel_launch(void* const* d_in, const int* in_sizes, int n_in,
                              void* d_out, int out_size)
{
    const float* x     = (const float*)d_in[0];
    const int*   erows = (const int*)d_in[1];
    const int*   ecols = (const int*)d_in[2];
    const float* evals = (const float*)d_in[3];
    const float* w     = (const float*)d_in[4];
    const float* b     = (const float*)d_in[5];
    float* out = (float*)d_out;

    const int M = in_sizes[0] / F_IN;     // 100000
    const int E = in_sizes[1];            // 3200000

    __half* sup;
    int2* edata;
    int *counts, *offsets, *cursor, *blocksums;
    cudaGetSymbolAddress((void**)&sup,       g_support_h);
    cudaGetSymbolAddress((void**)&edata,     g_edata);
    cudaGetSymbolAddress((void**)&counts,    g_counts);
    cudaGetSymbolAddress((void**)&offsets,   g_offsets);
    cudaGetSymbolAddress((void**)&cursor,    g_cursor);
    cudaGetSymbolAddress((void**)&blocksums, g_blocksums);

    // One-time host-side stream/event creation (no device memory involved).
    static cudaStream_t sGemm = nullptr;
    static cudaEvent_t evFork = nullptr, evGemmDone = nullptr;
    if (sGemm == nullptr) {
        cudaStreamCreateWithFlags(&sGemm, cudaStreamNonBlocking);
        cudaEventCreateWithFlags(&evFork, cudaEventDisableTiming);
        cudaEventCreateWithFlags(&evGemmDone, cudaEventDisableTiming);
    }

    // Fork: GEMM on side stream, edge counting-sort on main (capture) stream.
    cudaEventRecord(evFork, 0);
    cudaStreamWaitEvent(sGemm, evFork, 0);

    // --- side stream: TF32 tensor-core GEMM -> fp16 support ---
    {
        dim3 grid(F_OUT / GBN, (M + GBM - 1) / GBM);
        gemm_tc_kernel<<<grid, 256, 0, sGemm>>>(x, w, sup, M);
    }
    cudaEventRecord(evGemmDone, sGemm);

    // --- main stream: counting sort of edges by row ---
    const int nchunks = (M + SCAN_CHUNK - 1) / SCAN_CHUNK;
    zero_counts_kernel<<<(M + 255) / 256, 256>>>(counts, M);
    hist_kernel<<<592, 256>>>(erows, counts, E);
    scan_pass1<<<nchunks, SCAN_CHUNK>>>(counts, offsets, blocksums, M);
    scan_pass2<<<1, 128>>>(blocksums, offsets + M, nchunks);
    scan_pass3<<<nchunks, SCAN_CHUNK>>>(offsets, cursor, blocksums, M);
    scatter_kernel<<<592, 256>>>(erows, ecols, evals, cursor, edata, E);

    // Join: gather needs both the GEMM output and the sorted edges.
    cudaStreamWaitEvent(0, evGemmDone, 0);

    // --- Stage 3: warp-per-node reduction ---
    {
        int warpsPerBlock = 8;
        int blocks = (M + warpsPerBlock - 1) / warpsPerBlock;
        gather_reduce_kernel<<<blocks, 256>>>(offsets, edata, sup, b, out, M);
    }
}

// round 13
// speedup vs baseline: 1.0862x; 1.0862x over previous
#include <cuda_runtime.h>
#include <cuda_fp16.h>
#include <cuda_bf16.h>
#include <cstdint>

#define N_NODES 100000
#define F_IN 256
#define F_OUT 256
#define MAX_E 3200000

#define SCAN_CHUNK 1024
#define N_CHUNKS ((N_NODES + SCAN_CHUNK - 1) / SCAN_CHUNK)   // 98

// ---- device scratch ----
__device__ __half g_support_h[(size_t)N_NODES * F_OUT];  // 51.2 MB (fp16)
__device__ int2   g_edata[MAX_E];                        // packed (col, val)
__device__ int    g_counts[N_NODES];
__device__ int    g_offsets[N_NODES + 1];
__device__ int    g_cursor[N_NODES];
__device__ int    g_blocksums[N_CHUNKS];

// ---------------------------------------------------------------------------
// Stage 1: TF32 tensor-core GEMM  C[M,256] = A[M,256] @ B[256,256]
// ---------------------------------------------------------------------------
#define GBM 128
#define GBN 128
#define GBK 32
#define AS_STRIDE 36
#define BS_STRIDE 136

__device__ __forceinline__ uint32_t f32_to_tf32(float f)
{
    uint32_t u;
    asm volatile("cvt.rna.tf32.f32 %0, %1;" : "=r"(u) : "f"(f));
    return u;
}

__device__ __forceinline__ void mma_tf32(
    float& d0, float& d1, float& d2, float& d3,
    uint32_t a0, uint32_t a1, uint32_t a2, uint32_t a3,
    uint32_t b0, uint32_t b1)
{
    asm volatile(
        "mma.sync.aligned.m16n8k8.row.col.f32.tf32.tf32.f32 "
        "{%0,%1,%2,%3}, {%4,%5,%6,%7}, {%8,%9}, {%0,%1,%2,%3};\n"
        : "+f"(d0), "+f"(d1), "+f"(d2), "+f"(d3)
        : "r"(a0), "r"(a1), "r"(a2), "r"(a3), "r"(b0), "r"(b1));
}

__global__ void __launch_bounds__(256) gemm_tc_kernel(
    const float* __restrict__ A,
    const float* __restrict__ B,
    __half* __restrict__ C,
    int M)
{
    __shared__ uint32_t As[GBM][AS_STRIDE];
    __shared__ uint32_t Bs[GBK][BS_STRIDE];

    const int tid = threadIdx.x;
    const int lane = tid & 31;
    const int warp = tid >> 5;
    const int warpRow = warp >> 2;
    const int warpCol = warp & 3;
    const int blockRow = blockIdx.y * GBM;
    const int blockCol = blockIdx.x * GBN;

    const int lq = lane >> 2;
    const int lr = lane & 3;

    float d[4][4][4];
#pragma unroll
    for (int mt = 0; mt < 4; mt++)
#pragma unroll
        for (int nt = 0; nt < 4; nt++)
#pragma unroll
            for (int r = 0; r < 4; r++) d[mt][nt][r] = 0.0f;

    for (int k0 = 0; k0 < F_IN; k0 += GBK) {
#pragma unroll
        for (int i = 0; i < 4; i++) {
            int idx = tid + i * 256;
            int row = idx >> 3;
            int kc = (idx & 7) * 4;
            int gr = blockRow + row;
            float4 a4 = make_float4(0.f, 0.f, 0.f, 0.f);
            if (gr < M)
                a4 = *reinterpret_cast<const float4*>(A + (size_t)gr * F_IN + k0 + kc);
            uint4 t;
            t.x = f32_to_tf32(a4.x);
            t.y = f32_to_tf32(a4.y);
            t.z = f32_to_tf32(a4.z);
            t.w = f32_to_tf32(a4.w);
            *reinterpret_cast<uint4*>(&As[row][kc]) = t;
        }
#pragma unroll
        for (int i = 0; i < 4; i++) {
            int idx = tid + i * 256;
            int row = idx >> 5;
            int cc = (idx & 31) * 4;
            float4 b4 = *reinterpret_cast<const float4*>(
                B + (size_t)(k0 + row) * F_OUT + blockCol + cc);
            uint4 t;
            t.x = f32_to_tf32(b4.x);
            t.y = f32_to_tf32(b4.y);
            t.z = f32_to_tf32(b4.z);
            t.w = f32_to_tf32(b4.w);
            *reinterpret_cast<uint4*>(&Bs[row][cc]) = t;
        }
        __syncthreads();

#pragma unroll
        for (int kk = 0; kk < GBK; kk += 8) {
            uint32_t af[4][4];
#pragma unroll
            for (int mt = 0; mt < 4; mt++) {
                int r0 = warpRow * 64 + mt * 16 + lq;
                af[mt][0] = As[r0][kk + lr];
                af[mt][1] = As[r0 + 8][kk + lr];
                af[mt][2] = As[r0][kk + lr + 4];
                af[mt][3] = As[r0 + 8][kk + lr + 4];
            }
            uint32_t bf[4][2];
#pragma unroll
            for (int nt = 0; nt < 4; nt++) {
                int n0 = warpCol * 32 + nt * 8 + lq;
                bf[nt][0] = Bs[kk + lr][n0];
                bf[nt][1] = Bs[kk + lr + 4][n0];
            }
#pragma unroll
            for (int mt = 0; mt < 4; mt++)
#pragma unroll
                for (int nt = 0; nt < 4; nt++)
                    mma_tf32(d[mt][nt][0], d[mt][nt][1], d[mt][nt][2], d[mt][nt][3],
                             af[mt][0], af[mt][1], af[mt][2], af[mt][3],
                             bf[nt][0], bf[nt][1]);
        }
        __syncthreads();
    }

#pragma unroll
    for (int mt = 0; mt < 4; mt++) {
        int r0 = blockRow + warpRow * 64 + mt * 16 + lq;
        int r1 = r0 + 8;
#pragma unroll
        for (int nt = 0; nt < 4; nt++) {
            int c = blockCol + warpCol * 32 + nt * 8 + 2 * lr;
            if (r0 < M)
                *reinterpret_cast<__half2*>(C + (size_t)r0 * F_OUT + c) =
                    __floats2half2_rn(d[mt][nt][0], d[mt][nt][1]);
            if (r1 < M)
                *reinterpret_cast<__half2*>(C + (size_t)r1 * F_OUT + c) =
                    __floats2half2_rn(d[mt][nt][2], d[mt][nt][3]);
        }
    }
}

// ---------------------------------------------------------------------------
// Counting sort of edges by row
// ---------------------------------------------------------------------------
__global__ void zero_counts_kernel(int* __restrict__ counts, int n)
{
    int i = blockIdx.x * blockDim.x + threadIdx.x;
    if (i < n) counts[i] = 0;
}

__global__ void hist_kernel(const int* __restrict__ rows, int* __restrict__ counts, int E)
{
    const int4* r4 = reinterpret_cast<const int4*>(rows);
    int n4 = E >> 2;
    int i = blockIdx.x * blockDim.x + threadIdx.x;
    int stride = gridDim.x * blockDim.x;
    for (; i < n4; i += stride) {
        int4 r = __ldcs(&r4[i]);
        atomicAdd(&counts[r.x], 1);
        atomicAdd(&counts[r.y], 1);
        atomicAdd(&counts[r.z], 1);
        atomicAdd(&counts[r.w], 1);
    }
    int t = n4 * 4 + (blockIdx.x * blockDim.x + threadIdx.x);
    if (t < E) atomicAdd(&counts[rows[t]], 1);
}

__global__ void __launch_bounds__(1024) scan_pass1(
    const int* __restrict__ counts,
    int* __restrict__ offsets,
    int* __restrict__ blocksums, int n)
{
    __shared__ int sdata[SCAN_CHUNK];
    int tid = threadIdx.x;
    int i = blockIdx.x * SCAN_CHUNK + tid;
    int x = (i < n) ? counts[i] : 0;
    sdata[tid] = x;
    __syncthreads();
#pragma unroll
    for (int off = 1; off < SCAN_CHUNK; off <<= 1) {
        int t = (tid >= off) ? sdata[tid - off] : 0;
        __syncthreads();
        sdata[tid] += t;
        __syncthreads();
    }
    if (i < n) offsets[i] = sdata[tid] - x;
    if (tid == SCAN_CHUNK - 1) blocksums[blockIdx.x] = sdata[tid];
}

__global__ void scan_pass2(int* __restrict__ blocksums, int* __restrict__ total_out, int nchunks)
{
    __shared__ int sdata[128];
    int tid = threadIdx.x;
    int x = (tid < nchunks) ? blocksums[tid] : 0;
    sdata[tid] = x;
    __syncthreads();
#pragma unroll
    for (int off = 1; off < 128; off <<= 1) {
        int t = (tid >= off) ? sdata[tid - off] : 0;
        __syncthreads();
        sdata[tid] += t;
        __syncthreads();
    }
    if (tid < nchunks) blocksums[tid] = sdata[tid] - x;
    if (tid == 127) *total_out = sdata[127];
}

__global__ void __launch_bounds__(1024) scan_pass3(
    int* __restrict__ offsets,
    int* __restrict__ cursor,
    const int* __restrict__ blocksums, int n)
{
    int i = blockIdx.x * SCAN_CHUNK + threadIdx.x;
    if (i < n) {
        int v = offsets[i] + blocksums[blockIdx.x];
        offsets[i] = v;
        cursor[i] = v;
    }
}

__global__ void scatter_kernel(const int* __restrict__ rows,
                               const int* __restrict__ cols,
                               const float* __restrict__ vals,
                               int* __restrict__ cursor,
                               int2* __restrict__ edata, int E)
{
    const int4*   r4 = reinterpret_cast<const int4*>(rows);
    const int4*   c4 = reinterpret_cast<const int4*>(cols);
    const float4* v4 = reinterpret_cast<const float4*>(vals);
    int n4 = E >> 2;
    int i = blockIdx.x * blockDim.x + threadIdx.x;
    int stride = gridDim.x * blockDim.x;
    for (; i < n4; i += stride) {
        int4   r = __ldcs(&r4[i]);
        int4   c = __ldcs(&c4[i]);
        float4 v = __ldcs(&v4[i]);
        int p0 = atomicAdd(&cursor[r.x], 1);
        int p1 = atomicAdd(&cursor[r.y], 1);
        int p2 = atomicAdd(&cursor[r.z], 1);
        int p3 = atomicAdd(&cursor[r.w], 1);
        edata[p0] = make_int2(c.x, __float_as_int(v.x));
        edata[p1] = make_int2(c.y, __float_as_int(v.y));
        edata[p2] = make_int2(c.z, __float_as_int(v.z));
        edata[p3] = make_int2(c.w, __float_as_int(v.w));
    }
    int t = n4 * 4 + (blockIdx.x * blockDim.x + threadIdx.x);
    if (t < E) {
        int r = rows[t];
        int pos = atomicAdd(&cursor[r], 1);
        edata[pos] = make_int2(cols[t], __float_as_int(vals[t]));
    }
}

// ---------------------------------------------------------------------------
// Stage 3: warp-per-node segmented reduction, 4-edge unroll (R9 config).
// ---------------------------------------------------------------------------
__device__ __forceinline__ void acc_edge(float (&acc)[8], float v, const uint4& p)
{
    const __half2* h = reinterpret_cast<const __half2*>(&p);
#pragma unroll
    for (int j = 0; j < 4; j++) {
        float2 f = __half22float2(h[j]);
        acc[2 * j]     = fmaf(v, f.x, acc[2 * j]);
        acc[2 * j + 1] = fmaf(v, f.y, acc[2 * j + 1]);
    }
}

__global__ void __launch_bounds__(256) gather_reduce_kernel(
    const int* __restrict__ offsets,
    const int2* __restrict__ edata,
    const __half* __restrict__ sup,
    const float* __restrict__ bias,
    float* __restrict__ out,
    int M)
{
    int warp = (int)((blockIdx.x * blockDim.x + threadIdx.x) >> 5);
    int lane = threadIdx.x & 31;
    if (warp >= M) return;

    int start = offsets[warp];
    int end   = offsets[warp + 1];

    float acc[8];
#pragma unroll
    for (int j = 0; j < 8; j++) acc[j] = 0.0f;

    int e = start;
    int e4end = start + ((end - start) & ~3);
    for (; e < e4end; e += 4) {
        int2 ed0 = __ldcs(&edata[e]);
        int2 ed1 = __ldcs(&edata[e + 1]);
        int2 ed2 = __ldcs(&edata[e + 2]);
        int2 ed3 = __ldcs(&edata[e + 3]);
        uint4 p0 = reinterpret_cast<const uint4*>(sup + (size_t)ed0.x * F_OUT)[lane];
        uint4 p1 = reinterpret_cast<const uint4*>(sup + (size_t)ed1.x * F_OUT)[lane];
        uint4 p2 = reinterpret_cast<const uint4*>(sup + (size_t)ed2.x * F_OUT)[lane];
        uint4 p3 = reinterpret_cast<const uint4*>(sup + (size_t)ed3.x * F_OUT)[lane];
        acc_edge(acc, __int_as_float(ed0.y), p0);
        acc_edge(acc, __int_as_float(ed1.y), p1);
        acc_edge(acc, __int_as_float(ed2.y), p2);
        acc_edge(acc, __int_as_float(ed3.y), p3);
    }
    for (; e < end; e++) {
        int2 ed = __ldcs(&edata[e]);
        uint4 p = reinterpret_cast<const uint4*>(sup + (size_t)ed.x * F_OUT)[lane];
        acc_edge(acc, __int_as_float(ed.y), p);
    }

    const float4* b4 = reinterpret_cast<const float4*>(bias) + lane * 2;
    float4 bb0 = b4[0];
    float4 bb1 = b4[1];
    float4 o0 = make_float4(acc[0] + bb0.x, acc[1] + bb0.y, acc[2] + bb0.z, acc[3] + bb0.w);
    float4 o1 = make_float4(acc[4] + bb1.x, acc[5] + bb1.y, acc[6] + bb1.z, acc[7] + bb1.w);

    float4* orow = reinterpret_cast<float4*>(out + (size_t)warp * F_OUT) + lane * 2;
    __stcs(&orow[0], o0);
    __stcs(&orow[1], o1);
}

// ---------------------------------------------------------------------------
extern "C" void kernel_launch(void* const* d_in, const int* in_sizes, int n_in,
                              void* d_out, int out_size)
{
    const float* x     = (const float*)d_in[0];
    const int*   erows = (const int*)d_in[1];
    const int*   ecols = (const int*)d_in[2];
    const float* evals = (const float*)d_in[3];
    const float* w     = (const float*)d_in[4];
    const float* b     = (const float*)d_in[5];
    float* out = (float*)d_out;

    const int M = in_sizes[0] / F_IN;     // 100000
    const int E = in_sizes[1];            // 3200000

    __half* sup;
    int2* edata;
    int *counts, *offsets, *cursor, *blocksums;
    cudaGetSymbolAddress((void**)&sup,       g_support_h);
    cudaGetSymbolAddress((void**)&edata,     g_edata);
    cudaGetSymbolAddress((void**)&counts,    g_counts);
    cudaGetSymbolAddress((void**)&offsets,   g_offsets);
    cudaGetSymbolAddress((void**)&cursor,    g_cursor);
    cudaGetSymbolAddress((void**)&blocksums, g_blocksums);

    // One-time host-side stream/event creation (no device memory involved).
    static cudaStream_t sGemm = nullptr;
    static cudaEvent_t evFork = nullptr, evGemmDone = nullptr;
    if (sGemm == nullptr) {
        cudaStreamCreateWithFlags(&sGemm, cudaStreamNonBlocking);
        cudaEventCreateWithFlags(&evFork, cudaEventDisableTiming);
        cudaEventCreateWithFlags(&evGemmDone, cudaEventDisableTiming);
    }

    // Fork: GEMM on side stream, edge counting-sort on main (capture) stream.
    cudaEventRecord(evFork, 0);
    cudaStreamWaitEvent(sGemm, evFork, 0);

    // --- side stream: TF32 tensor-core GEMM -> fp16 support ---
    {
        dim3 grid(F_OUT / GBN, (M + GBM - 1) / GBM);
        gemm_tc_kernel<<<grid, 256, 0, sGemm>>>(x, w, sup, M);
    }
    cudaEventRecord(evGemmDone, sGemm);

    // --- main stream: counting sort of edges by row ---
    const int nchunks = (M + SCAN_CHUNK - 1) / SCAN_CHUNK;
    zero_counts_kernel<<<(M + 255) / 256, 256>>>(counts, M);
    hist_kernel<<<592, 256>>>(erows, counts, E);
    scan_pass1<<<nchunks, SCAN_CHUNK>>>(counts, offsets, blocksums, M);
    scan_pass2<<<1, 128>>>(blocksums, offsets + M, nchunks);
    scan_pass3<<<nchunks, SCAN_CHUNK>>>(offsets, cursor, blocksums, M);
    scatter_kernel<<<592, 256>>>(erows, ecols, evals, cursor, edata, E);

    // Join: gather needs both the GEMM output and the sorted edges.
    cudaStreamWaitEvent(0, evGemmDone, 0);

    // --- Stage 3: warp-per-node reduction (R9 config: 8 warps / 256 thr) ---
    {
        int warpsPerBlock = 8;
        int blocks = (M + warpsPerBlock - 1) / warpsPerBlock;
        gather_reduce_kernel<<<blocks, 256>>>(offsets, edata, sup, b, out, M);
    }
}